// round 15
// baseline (speedup 1.0000x reference)
#include <cuda_runtime.h>
#include <cuda_fp16.h>
#include <cstdint>
#include <math.h>

// ---------------------------------------------------------------------------
// Problem constants
// ---------------------------------------------------------------------------
#define T_TOK   8192
#define D_MODEL 1024
#define F_FF    2048
#define NE      8
#define CAP     2560
#define NA      (T_TOK * 2)

#define BM      128
#define BN      128
#define NRB     (CAP / BM)                  // 20
#define G1B     (NE * NRB * (F_FF / BN))    // 2560
#define G2B     (NE * NRB * (D_MODEL / BN)) // 1280

#define CONV_GRID 1184

// ---------------------------------------------------------------------------
// Device scratch
// ---------------------------------------------------------------------------
__device__ __half g_xh [(size_t)T_TOK * D_MODEL];       // fp16 x
__device__ __half g_w1h[(size_t)NE * D_MODEL * F_FF];   // fp16 w1 [e][k][f]
__device__ __half g_w2h[(size_t)NE * F_FF * D_MODEL];   // fp16 w2 [e][f][d]
__device__ __half g_Hh [(size_t)NE * CAP * F_FF];       // gelu output fp16
__device__ int    g_topk_i[NA];
__device__ float  g_topk_w[NA];
__device__ int    g_slot_tok[NE * CAP];
__device__ float  g_slot_w[NE * CAP];
__device__ int    g_cnt[NE];
__device__ int    g_ready[NE * NRB];                    // gemm1 col-tile counters
__device__ int    g_w2done;                             // conv2 completion counter

// ---------------------------------------------------------------------------
// Helpers
// ---------------------------------------------------------------------------
__device__ __forceinline__ uint32_t smem_u32(const void* p) {
    uint32_t a;
    asm("{ .reg .u64 t; cvta.to.shared.u64 t, %1; cvt.u32.u64 %0, t; }" : "=r"(a) : "l"(p));
    return a;
}
__device__ __forceinline__ void cp16(uint32_t dst, const void* src) {
    asm volatile("cp.async.cg.shared.global [%0], [%1], 16;" :: "r"(dst), "l"(src));
}
__device__ __forceinline__ void mma16(float* d, const uint32_t* a, const uint32_t* b) {
    asm volatile(
        "mma.sync.aligned.m16n8k16.row.col.f32.f16.f16.f32 "
        "{%0,%1,%2,%3}, {%4,%5,%6,%7}, {%8,%9}, {%0,%1,%2,%3};"
        : "+f"(d[0]), "+f"(d[1]), "+f"(d[2]), "+f"(d[3])
        : "r"(a[0]), "r"(a[1]), "r"(a[2]), "r"(a[3]), "r"(b[0]), "r"(b[1]));
}
__device__ __forceinline__ void red2(float* p, float v0, float v1) {
    asm volatile("red.global.add.v2.f32 [%0], {%1, %2};" :: "l"(p), "f"(v0), "f"(v1) : "memory");
}
#define LDSM4(r0, r1, r2, r3, a) \
    asm volatile("ldmatrix.sync.aligned.m8n8.x4.shared.b16 {%0,%1,%2,%3}, [%4];" \
                 : "=r"(r0), "=r"(r1), "=r"(r2), "=r"(r3) : "r"(a))
#define LDSM4T(r0, r1, r2, r3, a) \
    asm volatile("ldmatrix.sync.aligned.m8n8.x4.trans.shared.b16 {%0,%1,%2,%3}, [%4];" \
                 : "=r"(r0), "=r"(r1), "=r"(r2), "=r"(r3) : "r"(a))

#define ASTG    16384                    // A: 128 m-rows * 128B
#define BSTG    16384                    // B: 64 k-rows * 256B
#define STAGEB  (ASTG + BSTG)            // 32 KB
#define NSTAGE  3
#define DSMEM_BYTES (NSTAGE * STAGEB)    // 96 KB -> 2 CTAs/SM

// ---------------------------------------------------------------------------
// K0: zero output
// ---------------------------------------------------------------------------
__global__ void zero_kernel(float4* __restrict__ out, int n4) {
    int i = blockIdx.x * blockDim.x + threadIdx.x;
    if (i < n4) out[i] = make_float4(0.f, 0.f, 0.f, 0.f);
}

// ---------------------------------------------------------------------------
// K1a: conv w1 -> fp16; also resets g_w2done (stream-ordered before conv2)
// ---------------------------------------------------------------------------
__global__ __launch_bounds__(256)
void conv1_kernel(const float4* __restrict__ s, __half2* __restrict__ d, int n4) {
    if (blockIdx.x == 0 && threadIdx.x == 0) g_w2done = 0;
    int stride = gridDim.x * 256;
    for (int i = blockIdx.x * 256 + threadIdx.x; i < n4; i += stride) {
        float4 v = s[i];
        d[2 * i + 0] = __floats2half2_rn(v.x, v.y);
        d[2 * i + 1] = __floats2half2_rn(v.z, v.w);
    }
}

// ---------------------------------------------------------------------------
// K1b: conv w2 -> fp16; each block signals completion (gemm2 spins on it)
// ---------------------------------------------------------------------------
__global__ __launch_bounds__(256)
void conv2_kernel(const float4* __restrict__ s, __half2* __restrict__ d, int n4) {
    int stride = gridDim.x * 256;
    for (int i = blockIdx.x * 256 + threadIdx.x; i < n4; i += stride) {
        float4 v = s[i];
        d[2 * i + 0] = __floats2half2_rn(v.x, v.y);
        d[2 * i + 1] = __floats2half2_rn(v.z, v.w);
    }
    __threadfence();
    __syncthreads();
    if (threadIdx.x == 0) atomicAdd(&g_w2done, 1);
}

// ---------------------------------------------------------------------------
// K2: router + x->fp16 (one warp per token)
// ---------------------------------------------------------------------------
__global__ void router_kernel(const float* __restrict__ x,
                              const float* __restrict__ rw,
                              const float* __restrict__ rb) {
    int warp = (blockIdx.x * blockDim.x + threadIdx.x) >> 5;
    int lane = threadIdx.x & 31;
    if (warp >= T_TOK) return;
    const float* xr = x + (size_t)warp * D_MODEL;
    __half* xo = g_xh + (size_t)warp * D_MODEL;
    float acc[NE];
#pragma unroll
    for (int e = 0; e < NE; e++) acc[e] = 0.f;
    for (int d = lane; d < D_MODEL; d += 32) {
        float xv = xr[d];
        xo[d] = __float2half_rn(xv);
        const float* w = rw + d * NE;
#pragma unroll
        for (int e = 0; e < NE; e++) acc[e] += xv * w[e];
    }
#pragma unroll
    for (int e = 0; e < NE; e++)
#pragma unroll
        for (int o = 16; o > 0; o >>= 1)
            acc[e] += __shfl_down_sync(0xffffffffu, acc[e], o);
    if (lane == 0) {
        float l[NE];
#pragma unroll
        for (int e = 0; e < NE; e++) l[e] = acc[e] + rb[e];
        float m = l[0];
#pragma unroll
        for (int e = 1; e < NE; e++) m = fmaxf(m, l[e]);
        float p[NE], s = 0.f;
#pragma unroll
        for (int e = 0; e < NE; e++) { p[e] = expf(l[e] - m); s += p[e]; }
        float inv = 1.f / s;
#pragma unroll
        for (int e = 0; e < NE; e++) p[e] *= inv;
        int i1 = 0; float p1 = p[0];
#pragma unroll
        for (int e = 1; e < NE; e++) if (p[e] > p1) { p1 = p[e]; i1 = e; }
        int i2 = -1; float p2 = -1.f;
#pragma unroll
        for (int e = 0; e < NE; e++) if (e != i1 && p[e] > p2) { p2 = p[e]; i2 = e; }
        float sum = fmaxf(p1 + p2, 1e-9f);
        g_topk_i[warp * 2 + 0] = i1;
        g_topk_i[warp * 2 + 1] = i2;
        g_topk_w[warp * 2 + 0] = p1 / sum;
        g_topk_w[warp * 2 + 1] = p2 / sum;
    }
}

// ---------------------------------------------------------------------------
// K3: stable rank / capacity / slot table / zero readiness (single block)
// ---------------------------------------------------------------------------
__global__ void rank_kernel() {
    __shared__ int cnts[256][NE];
    int tid = threadIdx.x;
    if (tid < NE * NRB) g_ready[tid] = 0;
    int base = tid * (NA / 256);
    int local[NE];
#pragma unroll
    for (int e = 0; e < NE; e++) local[e] = 0;
    for (int a = base; a < base + NA / 256; a++) local[g_topk_i[a]]++;
#pragma unroll
    for (int e = 0; e < NE; e++) cnts[tid][e] = local[e];
    __syncthreads();
    if (tid < NE) {
        int run = 0;
        for (int i = 0; i < 256; i++) { int t = cnts[i][tid]; cnts[i][tid] = run; run += t; }
        g_cnt[tid] = min(run, CAP);
    }
    __syncthreads();
#pragma unroll
    for (int e = 0; e < NE; e++) local[e] = cnts[tid][e];
    for (int a = base; a < base + NA / 256; a++) {
        int e = g_topk_i[a];
        int r = local[e]++;
        if (r < CAP) {
            g_slot_tok[e * CAP + r] = a >> 1;
            g_slot_w[e * CAP + r] = g_topk_w[a];
        }
    }
}

// ---------------------------------------------------------------------------
// GEMM compute: one 64-half K-chunk. 8 warps 2m x 4n; warp tile 64x32.
// ---------------------------------------------------------------------------
__device__ __forceinline__ void compute_stage(uint32_t sA, uint32_t sB,
                                              int warp_m, int warp_n, int lane,
                                              float acc[4][4][4]) {
    int cg_a = lane >> 4;
    int la15 = lane & 15;
    int kl = lane & 15;
    int ng = lane >> 4;
#pragma unroll
    for (int k16 = 0; k16 < 4; k16++) {
        uint32_t af[4][4];
#pragma unroll
        for (int mt = 0; mt < 4; mt++) {
            int row = warp_m + mt * 16 + la15;
            uint32_t addr = sA + (uint32_t)(row << 7)
                          + (uint32_t)((((k16 << 1) + cg_a) ^ (row & 7)) << 4);
            LDSM4(af[mt][0], af[mt][1], af[mt][2], af[mt][3], addr);
        }
        uint32_t bf[4][2];
#pragma unroll
        for (int p = 0; p < 2; p++) {
            int kr = k16 * 16 + kl;
            int nn = warp_n + p * 16 + ng * 8;
            uint32_t addr = sB + (uint32_t)(kr << 8)
                          + (uint32_t)((((nn >> 3) ^ (kr & 7))) << 4);
            LDSM4T(bf[2 * p][0], bf[2 * p][1], bf[2 * p + 1][0], bf[2 * p + 1][1], addr);
        }
#pragma unroll
        for (int mt = 0; mt < 4; mt++)
#pragma unroll
            for (int nt = 0; nt < 4; nt++)
                mma16(acc[mt][nt], af[mt], bf[nt]);
    }
}

// ---------------------------------------------------------------------------
// K4: fused GEMM1 + GEMM2, single launch, 2 CTAs/SM.
// Single-barrier mainloop; gemm2 spins on conv2 completion + gemm1 tiles.
// ---------------------------------------------------------------------------
__global__ __launch_bounds__(256, 2)
void fused_gemm_kernel(const float* __restrict__ b1,
                       const float* __restrict__ b2,
                       float* __restrict__ out) {
    extern __shared__ __align__(128) char smem[];
    uint32_t sb = smem_u32(smem);
    int tid = threadIdx.x;
    int wid = tid >> 5, lane = tid & 31;
    int warp_m = (wid >> 2) * 64, warp_n = (wid & 3) * 32;
    int g = lane >> 2, t4 = lane & 3;
    int bid = blockIdx.x;

    if (bid < G1B) {
        // ---------------- GEMM1 tile ----------------
        int cb = bid & 15;
        int erb = bid >> 4;
        int e = erb / NRB;
        int row0 = (erb % NRB) * BM;
        int cnt = g_cnt[e];
        if (row0 >= cnt) return;
        int col0 = cb * BN;

        int c8 = tid & 7;
        int rbt = tid >> 3;
        const __half* aP[4];
        uint32_t stA[4];
#pragma unroll
        for (int q = 0; q < 4; q++) {
            int r = rbt + 32 * q;
            int grow = row0 + r;
            int tok = (grow < cnt) ? g_slot_tok[e * CAP + grow] : 0;
            aP[q] = g_xh + (size_t)tok * D_MODEL + c8 * 8;
            stA[q] = sb + (uint32_t)((r << 7) + ((c8 ^ (r & 7)) << 4));
        }
        int c16 = tid & 15;
        int rk = tid >> 4;
        const __half* w1e = g_w1h + (size_t)e * D_MODEL * F_FF;
        const __half* bP[4];
        uint32_t stB[4];
#pragma unroll
        for (int q = 0; q < 4; q++) {
            int r = rk + 16 * q;
            bP[q] = w1e + (size_t)r * F_FF + col0 + c16 * 8;
            stB[q] = sb + ASTG + (uint32_t)((r << 8) + ((c16 ^ (r & 7)) << 4));
        }

        float acc[4][4][4];
#pragma unroll
        for (int mt = 0; mt < 4; mt++)
#pragma unroll
            for (int nt = 0; nt < 4; nt++)
#pragma unroll
                for (int k = 0; k < 4; k++) acc[mt][nt][k] = 0.f;

        const int NCH = D_MODEL / 64;   // 16
#pragma unroll
        for (int c = 0; c < 2; c++) {
            uint32_t so = (uint32_t)(c * STAGEB);
#pragma unroll
            for (int q = 0; q < 4; q++) {
                cp16(stA[q] + so, aP[q]); aP[q] += 64;
                cp16(stB[q] + so, bP[q]); bP[q] += (size_t)64 * F_FF;
            }
            asm volatile("cp.async.commit_group;" ::: "memory");
        }
        for (int i = 0; i < NCH; i++) {
            if (i < NCH - 1) {
                asm volatile("cp.async.wait_group 1;" ::: "memory");
            } else {
                asm volatile("cp.async.wait_group 0;" ::: "memory");
            }
            __syncthreads();
            if (i + 2 < NCH) {
                uint32_t so = (uint32_t)(((i + 2) % NSTAGE) * STAGEB);
#pragma unroll
                for (int q = 0; q < 4; q++) {
                    cp16(stA[q] + so, aP[q]); aP[q] += 64;
                    cp16(stB[q] + so, bP[q]); bP[q] += (size_t)64 * F_FF;
                }
                asm volatile("cp.async.commit_group;" ::: "memory");
            }
            uint32_t stg = sb + (uint32_t)((i % NSTAGE) * STAGEB);
            compute_stage(stg, stg + ASTG, warp_m, warp_n, lane, acc);
        }

        // epilogue: bias + gelu -> H fp16
        const float* bp = b1 + e * F_FF + col0;
#pragma unroll
        for (int mt = 0; mt < 4; mt++) {
#pragma unroll
            for (int h = 0; h < 2; h++) {
                int r = row0 + warp_m + mt * 16 + g + h * 8;
                __half* Hrow = g_Hh + ((size_t)e * CAP + r) * F_FF + col0;
#pragma unroll
                for (int nt = 0; nt < 4; nt++) {
                    int c = warp_n + nt * 8 + 2 * t4;
                    float v0 = acc[mt][nt][2 * h + 0] + bp[c];
                    float v1 = acc[mt][nt][2 * h + 1] + bp[c + 1];
                    v0 = 0.5f * v0 * (1.f + erff(v0 * 0.70710678118654752f));
                    v1 = 0.5f * v1 * (1.f + erff(v1 * 0.70710678118654752f));
                    *(__half2*)(Hrow + c) = __floats2half2_rn(v0, v1);
                }
            }
        }
        __syncthreads();
        if (tid == 0) {
            __threadfence();
            atomicAdd(&g_ready[erb], 1);
        }
    } else {
        // ---------------- GEMM2 tile ----------------
        int b2id = bid - G1B;
        int cb = b2id & 7;
        int erb = b2id >> 3;
        int e = erb / NRB;
        int row0 = (erb % NRB) * BM;
        int cnt = g_cnt[e];
        if (row0 >= cnt) return;
        int col0 = cb * BN;

        if (tid == 0) {
            while (atomicAdd(&g_w2done, 0) < CONV_GRID) __nanosleep(200);
            while (atomicAdd(&g_ready[erb], 0) < 16) __nanosleep(200);
        }
        __syncthreads();
        __threadfence();

        int c8 = tid & 7;
        int rbt = tid >> 3;
        const __half* aP[4];
        uint32_t stA[4];
        const __half* He = g_Hh + (size_t)e * CAP * F_FF;
#pragma unroll
        for (int q = 0; q < 4; q++) {
            int r = rbt + 32 * q;
            aP[q] = He + (size_t)(row0 + r) * F_FF + c8 * 8;
            stA[q] = sb + (uint32_t)((r << 7) + ((c8 ^ (r & 7)) << 4));
        }
        int c16 = tid & 15;
        int rk = tid >> 4;
        const __half* w2e = g_w2h + (size_t)e * F_FF * D_MODEL;
        const __half* bP[4];
        uint32_t stB[4];
#pragma unroll
        for (int q = 0; q < 4; q++) {
            int r = rk + 16 * q;
            bP[q] = w2e + (size_t)r * D_MODEL + col0 + c16 * 8;
            stB[q] = sb + ASTG + (uint32_t)((r << 8) + ((c16 ^ (r & 7)) << 4));
        }

        float acc[4][4][4];
#pragma unroll
        for (int mt = 0; mt < 4; mt++)
#pragma unroll
            for (int nt = 0; nt < 4; nt++)
#pragma unroll
                for (int k = 0; k < 4; k++) acc[mt][nt][k] = 0.f;

        const int NCH = F_FF / 64;   // 32
#pragma unroll
        for (int c = 0; c < 2; c++) {
            uint32_t so = (uint32_t)(c * STAGEB);
#pragma unroll
            for (int q = 0; q < 4; q++) {
                cp16(stA[q] + so, aP[q]); aP[q] += 64;
                cp16(stB[q] + so, bP[q]); bP[q] += (size_t)64 * D_MODEL;
            }
            asm volatile("cp.async.commit_group;" ::: "memory");
        }
        for (int i = 0; i < NCH; i++) {
            if (i < NCH - 1) {
                asm volatile("cp.async.wait_group 1;" ::: "memory");
            } else {
                asm volatile("cp.async.wait_group 0;" ::: "memory");
            }
            __syncthreads();
            if (i + 2 < NCH) {
                uint32_t so = (uint32_t)(((i + 2) % NSTAGE) * STAGEB);
#pragma unroll
                for (int q = 0; q < 4; q++) {
                    cp16(stA[q] + so, aP[q]); aP[q] += 64;
                    cp16(stB[q] + so, bP[q]); bP[q] += (size_t)64 * D_MODEL;
                }
                asm volatile("cp.async.commit_group;" ::: "memory");
            }
            uint32_t stg = sb + (uint32_t)((i % NSTAGE) * STAGEB);
            compute_stage(stg, stg + ASTG, warp_m, warp_n, lane, acc);
        }

        // epilogue: bias + gate + vector-red scatter
        const float* bp = b2 + e * D_MODEL + col0;
#pragma unroll
        for (int mt = 0; mt < 4; mt++) {
#pragma unroll
            for (int h = 0; h < 2; h++) {
                int r = row0 + warp_m + mt * 16 + g + h * 8;
                if (r < cnt) {
                    int   tok = g_slot_tok[e * CAP + r];
                    float w   = g_slot_w[e * CAP + r];
                    float* orow = out + (size_t)tok * D_MODEL + col0;
#pragma unroll
                    for (int nt = 0; nt < 4; nt++) {
                        int c = warp_n + nt * 8 + 2 * t4;
                        red2(orow + c,
                             (acc[mt][nt][2 * h + 0] + bp[c])     * w,
                             (acc[mt][nt][2 * h + 1] + bp[c + 1]) * w);
                    }
                }
            }
        }
    }
}

// ---------------------------------------------------------------------------
extern "C" void kernel_launch(void* const* d_in, const int* in_sizes, int n_in,
                              void* d_out, int out_size) {
    const float* x  = (const float*)d_in[0];
    const float* rw = (const float*)d_in[1];
    const float* rb = (const float*)d_in[2];
    const float* w1 = (const float*)d_in[3];
    const float* b1 = (const float*)d_in[4];
    const float* w2 = (const float*)d_in[5];
    const float* b2 = (const float*)d_in[6];
    float* out = (float*)d_out;

    cudaFuncSetAttribute(fused_gemm_kernel, cudaFuncAttributeMaxDynamicSharedMemorySize, DSMEM_BYTES);

    __half *w1h, *w2h;
    cudaGetSymbolAddress((void**)&w1h, g_w1h);
    cudaGetSymbolAddress((void**)&w2h, g_w2h);
    int wn4 = NE * D_MODEL * F_FF / 4;

    static cudaStream_t s2 = nullptr;
    static cudaEvent_t e0 = nullptr, e1 = nullptr, e2 = nullptr;
    if (!s2) {
        cudaStreamCreateWithFlags(&s2, cudaStreamNonBlocking);
        cudaEventCreateWithFlags(&e0, cudaEventDisableTiming);
        cudaEventCreateWithFlags(&e1, cudaEventDisableTiming);
        cudaEventCreateWithFlags(&e2, cudaEventDisableTiming);
    }

    // Fork converts onto s2 (branches from the capture-origin stream).
    cudaEventRecord(e0, 0);
    cudaStreamWaitEvent(s2, e0, 0);
    conv1_kernel<<<CONV_GRID, 256, 0, s2>>>((const float4*)w1, (__half2*)w1h, wn4);
    cudaEventRecord(e1, s2);                 // w1 ready
    conv2_kernel<<<CONV_GRID, 256, 0, s2>>>((const float4*)w2, (__half2*)w2h, wn4);
    cudaEventRecord(e2, s2);                 // join handle

    // Main chain.
    int n4 = out_size / 4;
    zero_kernel<<<(n4 + 255) / 256, 256>>>((float4*)out, n4);
    router_kernel<<<T_TOK / 8, 256>>>(x, rw, rb);
    rank_kernel<<<1, 256>>>();

    cudaStreamWaitEvent(0, e1, 0);           // gemm1 needs w1h
    fused_gemm_kernel<<<G1B + G2B, 256, DSMEM_BYTES>>>(b1, b2, out);
    cudaStreamWaitEvent(0, e2, 0);           // JOIN s2 back into capture stream
    // (the wait is after the GEMM launch, so conv2 overlaps the GEMM;
    //  gemm2's correctness w.r.t. w2h is enforced device-side via g_w2done)
}

// round 16
// speedup vs baseline: 1.1065x; 1.1065x over previous
#include <cuda_runtime.h>
#include <cuda_fp16.h>
#include <cstdint>
#include <math.h>

// ---------------------------------------------------------------------------
// Problem constants
// ---------------------------------------------------------------------------
#define T_TOK   8192
#define D_MODEL 1024
#define F_FF    2048
#define NE      8
#define CAP     2560
#define NA      (T_TOK * 2)

#define BM      128
#define BN      128
#define NRB     (CAP / BM)                  // 20
#define G1B     (NE * NRB * (F_FF / BN))    // 2560
#define G2B     (NE * NRB * (D_MODEL / BN)) // 1280

#define CONV_GRID 1184

// ---------------------------------------------------------------------------
// Device scratch
// ---------------------------------------------------------------------------
__device__ __half g_xh [(size_t)T_TOK * D_MODEL];       // fp16 x
__device__ __half g_w1h[(size_t)NE * D_MODEL * F_FF];   // fp16 w1 [e][k][f]
__device__ __half g_w2h[(size_t)NE * F_FF * D_MODEL];   // fp16 w2 [e][f][d]
__device__ __half g_Hh [(size_t)NE * CAP * F_FF];       // gelu output fp16
__device__ int    g_topk_i[NA];
__device__ float  g_topk_w[NA];
__device__ int    g_slot_tok[NE * CAP];
__device__ float  g_slot_w[NE * CAP];
__device__ int    g_cnt[NE];
__device__ int    g_ready[NE * NRB];                    // gemm1 col-tile counters
__device__ int    g_w2done;                             // conv2 completion counter

// ---------------------------------------------------------------------------
// Helpers
// ---------------------------------------------------------------------------
__device__ __forceinline__ uint32_t smem_u32(const void* p) {
    uint32_t a;
    asm("{ .reg .u64 t; cvta.to.shared.u64 t, %1; cvt.u32.u64 %0, t; }" : "=r"(a) : "l"(p));
    return a;
}
__device__ __forceinline__ void cp16(uint32_t dst, const void* src) {
    asm volatile("cp.async.cg.shared.global [%0], [%1], 16;" :: "r"(dst), "l"(src));
}
__device__ __forceinline__ void mma16(float* d, const uint32_t* a, const uint32_t* b) {
    asm volatile(
        "mma.sync.aligned.m16n8k16.row.col.f32.f16.f16.f32 "
        "{%0,%1,%2,%3}, {%4,%5,%6,%7}, {%8,%9}, {%0,%1,%2,%3};"
        : "+f"(d[0]), "+f"(d[1]), "+f"(d[2]), "+f"(d[3])
        : "r"(a[0]), "r"(a[1]), "r"(a[2]), "r"(a[3]), "r"(b[0]), "r"(b[1]));
}
__device__ __forceinline__ void red2(float* p, float v0, float v1) {
    asm volatile("red.global.add.v2.f32 [%0], {%1, %2};" :: "l"(p), "f"(v0), "f"(v1) : "memory");
}
#define LDSM4(r0, r1, r2, r3, a) \
    asm volatile("ldmatrix.sync.aligned.m8n8.x4.shared.b16 {%0,%1,%2,%3}, [%4];" \
                 : "=r"(r0), "=r"(r1), "=r"(r2), "=r"(r3) : "r"(a))
#define LDSM4T(r0, r1, r2, r3, a) \
    asm volatile("ldmatrix.sync.aligned.m8n8.x4.trans.shared.b16 {%0,%1,%2,%3}, [%4];" \
                 : "=r"(r0), "=r"(r1), "=r"(r2), "=r"(r3) : "r"(a))

#define ASTG    16384                    // A: 128 m-rows * 128B
#define BSTG    16384                    // B: 64 k-rows * 256B
#define STAGEB  (ASTG + BSTG)            // 32 KB
#define NSTAGE  3
#define DSMEM_BYTES (NSTAGE * STAGEB)    // 96 KB -> 2 CTAs/SM

// ---------------------------------------------------------------------------
// K0: zero output
// ---------------------------------------------------------------------------
__global__ void zero_kernel(float4* __restrict__ out, int n4) {
    int i = blockIdx.x * blockDim.x + threadIdx.x;
    if (i < n4) out[i] = make_float4(0.f, 0.f, 0.f, 0.f);
}

// ---------------------------------------------------------------------------
// K1a: conv w1 -> fp16; also resets g_w2done (stream-ordered before conv2)
// ---------------------------------------------------------------------------
__global__ __launch_bounds__(256)
void conv1_kernel(const float4* __restrict__ s, __half2* __restrict__ d, int n4) {
    if (blockIdx.x == 0 && threadIdx.x == 0) g_w2done = 0;
    int stride = gridDim.x * 256;
    for (int i = blockIdx.x * 256 + threadIdx.x; i < n4; i += stride) {
        float4 v = s[i];
        d[2 * i + 0] = __floats2half2_rn(v.x, v.y);
        d[2 * i + 1] = __floats2half2_rn(v.z, v.w);
    }
}

// ---------------------------------------------------------------------------
// K1b: conv w2 -> fp16; each block signals completion (gemm2 spins on it)
// ---------------------------------------------------------------------------
__global__ __launch_bounds__(256)
void conv2_kernel(const float4* __restrict__ s, __half2* __restrict__ d, int n4) {
    int stride = gridDim.x * 256;
    for (int i = blockIdx.x * 256 + threadIdx.x; i < n4; i += stride) {
        float4 v = s[i];
        d[2 * i + 0] = __floats2half2_rn(v.x, v.y);
        d[2 * i + 1] = __floats2half2_rn(v.z, v.w);
    }
    __threadfence();
    __syncthreads();
    if (threadIdx.x == 0) atomicAdd(&g_w2done, 1);
}

// ---------------------------------------------------------------------------
// K2: router + x->fp16. rw staged in smem padded to 9 floats/row:
// bank(d*9+e) = (9*lane+e) mod 32, gcd(9,32)=1 -> conflict-free LDS.
// ---------------------------------------------------------------------------
__global__ __launch_bounds__(256)
void router_kernel(const float* __restrict__ x,
                   const float* __restrict__ rw,
                   const float* __restrict__ rb) {
    __shared__ float rws[D_MODEL * 9];
    int tid = threadIdx.x;
    int wid = tid >> 5, lane = tid & 31;

    for (int i = tid; i < D_MODEL * NE; i += 256)
        rws[(i >> 3) * 9 + (i & 7)] = rw[i];
    __syncthreads();

    int tok = blockIdx.x * 8 + wid;
    const float* xr = x + (size_t)tok * D_MODEL;
    __half* xo = g_xh + (size_t)tok * D_MODEL;
    float acc[NE];
#pragma unroll
    for (int e = 0; e < NE; e++) acc[e] = 0.f;
    for (int d = lane; d < D_MODEL; d += 32) {
        float xv = xr[d];
        xo[d] = __float2half_rn(xv);
        const float* w = rws + d * 9;
#pragma unroll
        for (int e = 0; e < NE; e++) acc[e] += xv * w[e];
    }
#pragma unroll
    for (int e = 0; e < NE; e++)
#pragma unroll
        for (int o = 16; o > 0; o >>= 1)
            acc[e] += __shfl_down_sync(0xffffffffu, acc[e], o);
    if (lane == 0) {
        float l[NE];
#pragma unroll
        for (int e = 0; e < NE; e++) l[e] = acc[e] + rb[e];
        float m = l[0];
#pragma unroll
        for (int e = 1; e < NE; e++) m = fmaxf(m, l[e]);
        float p[NE], s = 0.f;
#pragma unroll
        for (int e = 0; e < NE; e++) { p[e] = expf(l[e] - m); s += p[e]; }
        float inv = 1.f / s;
#pragma unroll
        for (int e = 0; e < NE; e++) p[e] *= inv;
        int i1 = 0; float p1 = p[0];
#pragma unroll
        for (int e = 1; e < NE; e++) if (p[e] > p1) { p1 = p[e]; i1 = e; }
        int i2 = -1; float p2 = -1.f;
#pragma unroll
        for (int e = 0; e < NE; e++) if (e != i1 && p[e] > p2) { p2 = p[e]; i2 = e; }
        float sum = fmaxf(p1 + p2, 1e-9f);
        g_topk_i[tok * 2 + 0] = i1;
        g_topk_i[tok * 2 + 1] = i2;
        g_topk_w[tok * 2 + 0] = p1 / sum;
        g_topk_w[tok * 2 + 1] = p2 / sum;
    }
}

// ---------------------------------------------------------------------------
// K3: stable rank / capacity / slot table / zero readiness (single block)
// ---------------------------------------------------------------------------
__global__ void rank_kernel() {
    __shared__ int cnts[256][NE];
    int tid = threadIdx.x;
    if (tid < NE * NRB) g_ready[tid] = 0;
    int base = tid * (NA / 256);
    int local[NE];
#pragma unroll
    for (int e = 0; e < NE; e++) local[e] = 0;
    for (int a = base; a < base + NA / 256; a++) local[g_topk_i[a]]++;
#pragma unroll
    for (int e = 0; e < NE; e++) cnts[tid][e] = local[e];
    __syncthreads();
    if (tid < NE) {
        int run = 0;
        for (int i = 0; i < 256; i++) { int t = cnts[i][tid]; cnts[i][tid] = run; run += t; }
        g_cnt[tid] = min(run, CAP);
    }
    __syncthreads();
#pragma unroll
    for (int e = 0; e < NE; e++) local[e] = cnts[tid][e];
    for (int a = base; a < base + NA / 256; a++) {
        int e = g_topk_i[a];
        int r = local[e]++;
        if (r < CAP) {
            g_slot_tok[e * CAP + r] = a >> 1;
            g_slot_w[e * CAP + r] = g_topk_w[a];
        }
    }
}

// ---------------------------------------------------------------------------
// GEMM compute: one 64-half K-chunk. 8 warps 2m x 4n; warp tile 64x32.
// ---------------------------------------------------------------------------
__device__ __forceinline__ void compute_stage(uint32_t sA, uint32_t sB,
                                              int warp_m, int warp_n, int lane,
                                              float acc[4][4][4]) {
    int cg_a = lane >> 4;
    int la15 = lane & 15;
    int kl = lane & 15;
    int ng = lane >> 4;
#pragma unroll
    for (int k16 = 0; k16 < 4; k16++) {
        uint32_t af[4][4];
#pragma unroll
        for (int mt = 0; mt < 4; mt++) {
            int row = warp_m + mt * 16 + la15;
            uint32_t addr = sA + (uint32_t)(row << 7)
                          + (uint32_t)((((k16 << 1) + cg_a) ^ (row & 7)) << 4);
            LDSM4(af[mt][0], af[mt][1], af[mt][2], af[mt][3], addr);
        }
        uint32_t bf[4][2];
#pragma unroll
        for (int p = 0; p < 2; p++) {
            int kr = k16 * 16 + kl;
            int nn = warp_n + p * 16 + ng * 8;
            uint32_t addr = sB + (uint32_t)(kr << 8)
                          + (uint32_t)((((nn >> 3) ^ (kr & 7))) << 4);
            LDSM4T(bf[2 * p][0], bf[2 * p][1], bf[2 * p + 1][0], bf[2 * p + 1][1], addr);
        }
#pragma unroll
        for (int mt = 0; mt < 4; mt++)
#pragma unroll
            for (int nt = 0; nt < 4; nt++)
                mma16(acc[mt][nt], af[mt], bf[nt]);
    }
}

// ---------------------------------------------------------------------------
// K4: fused GEMM1 + GEMM2, single launch, 2 CTAs/SM.
// ---------------------------------------------------------------------------
__global__ __launch_bounds__(256, 2)
void fused_gemm_kernel(const float* __restrict__ b1,
                       const float* __restrict__ b2,
                       float* __restrict__ out) {
    extern __shared__ __align__(128) char smem[];
    uint32_t sb = smem_u32(smem);
    int tid = threadIdx.x;
    int wid = tid >> 5, lane = tid & 31;
    int warp_m = (wid >> 2) * 64, warp_n = (wid & 3) * 32;
    int g = lane >> 2, t4 = lane & 3;
    int bid = blockIdx.x;

    if (bid < G1B) {
        // ---------------- GEMM1 tile ----------------
        int cb = bid & 15;
        int erb = bid >> 4;
        int e = erb / NRB;
        int row0 = (erb % NRB) * BM;
        int cnt = g_cnt[e];
        if (row0 >= cnt) return;
        int col0 = cb * BN;

        int c8 = tid & 7;
        int rbt = tid >> 3;
        const __half* aP[4];
        uint32_t stA[4];
#pragma unroll
        for (int q = 0; q < 4; q++) {
            int r = rbt + 32 * q;
            int grow = row0 + r;
            int tok = (grow < cnt) ? g_slot_tok[e * CAP + grow] : 0;
            aP[q] = g_xh + (size_t)tok * D_MODEL + c8 * 8;
            stA[q] = sb + (uint32_t)((r << 7) + ((c8 ^ (r & 7)) << 4));
        }
        int c16 = tid & 15;
        int rk = tid >> 4;
        const __half* w1e = g_w1h + (size_t)e * D_MODEL * F_FF;
        const __half* bP[4];
        uint32_t stB[4];
#pragma unroll
        for (int q = 0; q < 4; q++) {
            int r = rk + 16 * q;
            bP[q] = w1e + (size_t)r * F_FF + col0 + c16 * 8;
            stB[q] = sb + ASTG + (uint32_t)((r << 8) + ((c16 ^ (r & 7)) << 4));
        }

        float acc[4][4][4];
#pragma unroll
        for (int mt = 0; mt < 4; mt++)
#pragma unroll
            for (int nt = 0; nt < 4; nt++)
#pragma unroll
                for (int k = 0; k < 4; k++) acc[mt][nt][k] = 0.f;

        const int NCH = D_MODEL / 64;   // 16
#pragma unroll
        for (int c = 0; c < 2; c++) {
            uint32_t so = (uint32_t)(c * STAGEB);
#pragma unroll
            for (int q = 0; q < 4; q++) {
                cp16(stA[q] + so, aP[q]); aP[q] += 64;
                cp16(stB[q] + so, bP[q]); bP[q] += (size_t)64 * F_FF;
            }
            asm volatile("cp.async.commit_group;" ::: "memory");
        }
        for (int i = 0; i < NCH; i++) {
            if (i < NCH - 1) {
                asm volatile("cp.async.wait_group 1;" ::: "memory");
            } else {
                asm volatile("cp.async.wait_group 0;" ::: "memory");
            }
            __syncthreads();
            if (i + 2 < NCH) {
                uint32_t so = (uint32_t)(((i + 2) % NSTAGE) * STAGEB);
#pragma unroll
                for (int q = 0; q < 4; q++) {
                    cp16(stA[q] + so, aP[q]); aP[q] += 64;
                    cp16(stB[q] + so, bP[q]); bP[q] += (size_t)64 * F_FF;
                }
                asm volatile("cp.async.commit_group;" ::: "memory");
            }
            uint32_t stg = sb + (uint32_t)((i % NSTAGE) * STAGEB);
            compute_stage(stg, stg + ASTG, warp_m, warp_n, lane, acc);
        }

        // epilogue: bias + gelu -> H fp16
        const float* bp = b1 + e * F_FF + col0;
#pragma unroll
        for (int mt = 0; mt < 4; mt++) {
#pragma unroll
            for (int h = 0; h < 2; h++) {
                int r = row0 + warp_m + mt * 16 + g + h * 8;
                __half* Hrow = g_Hh + ((size_t)e * CAP + r) * F_FF + col0;
#pragma unroll
                for (int nt = 0; nt < 4; nt++) {
                    int c = warp_n + nt * 8 + 2 * t4;
                    float v0 = acc[mt][nt][2 * h + 0] + bp[c];
                    float v1 = acc[mt][nt][2 * h + 1] + bp[c + 1];
                    v0 = 0.5f * v0 * (1.f + erff(v0 * 0.70710678118654752f));
                    v1 = 0.5f * v1 * (1.f + erff(v1 * 0.70710678118654752f));
                    *(__half2*)(Hrow + c) = __floats2half2_rn(v0, v1);
                }
            }
        }
        __syncthreads();
        if (tid == 0) {
            __threadfence();
            atomicAdd(&g_ready[erb], 1);
        }
    } else {
        // ---------------- GEMM2 tile ----------------
        int b2id = bid - G1B;
        int cb = b2id & 7;
        int erb = b2id >> 3;
        int e = erb / NRB;
        int row0 = (erb % NRB) * BM;
        int cnt = g_cnt[e];
        if (row0 >= cnt) return;
        int col0 = cb * BN;

        if (tid == 0) {
            while (atomicAdd(&g_w2done, 0) < CONV_GRID) __nanosleep(200);
            while (atomicAdd(&g_ready[erb], 0) < 16) __nanosleep(200);
        }
        __syncthreads();
        __threadfence();

        int c8 = tid & 7;
        int rbt = tid >> 3;
        const __half* aP[4];
        uint32_t stA[4];
        const __half* He = g_Hh + (size_t)e * CAP * F_FF;
#pragma unroll
        for (int q = 0; q < 4; q++) {
            int r = rbt + 32 * q;
            aP[q] = He + (size_t)(row0 + r) * F_FF + c8 * 8;
            stA[q] = sb + (uint32_t)((r << 7) + ((c8 ^ (r & 7)) << 4));
        }
        int c16 = tid & 15;
        int rk = tid >> 4;
        const __half* w2e = g_w2h + (size_t)e * F_FF * D_MODEL;
        const __half* bP[4];
        uint32_t stB[4];
#pragma unroll
        for (int q = 0; q < 4; q++) {
            int r = rk + 16 * q;
            bP[q] = w2e + (size_t)r * D_MODEL + col0 + c16 * 8;
            stB[q] = sb + ASTG + (uint32_t)((r << 8) + ((c16 ^ (r & 7)) << 4));
        }

        float acc[4][4][4];
#pragma unroll
        for (int mt = 0; mt < 4; mt++)
#pragma unroll
            for (int nt = 0; nt < 4; nt++)
#pragma unroll
                for (int k = 0; k < 4; k++) acc[mt][nt][k] = 0.f;

        const int NCH = F_FF / 64;   // 32
#pragma unroll
        for (int c = 0; c < 2; c++) {
            uint32_t so = (uint32_t)(c * STAGEB);
#pragma unroll
            for (int q = 0; q < 4; q++) {
                cp16(stA[q] + so, aP[q]); aP[q] += 64;
                cp16(stB[q] + so, bP[q]); bP[q] += (size_t)64 * D_MODEL;
            }
            asm volatile("cp.async.commit_group;" ::: "memory");
        }
        for (int i = 0; i < NCH; i++) {
            if (i < NCH - 1) {
                asm volatile("cp.async.wait_group 1;" ::: "memory");
            } else {
                asm volatile("cp.async.wait_group 0;" ::: "memory");
            }
            __syncthreads();
            if (i + 2 < NCH) {
                uint32_t so = (uint32_t)(((i + 2) % NSTAGE) * STAGEB);
#pragma unroll
                for (int q = 0; q < 4; q++) {
                    cp16(stA[q] + so, aP[q]); aP[q] += 64;
                    cp16(stB[q] + so, bP[q]); bP[q] += (size_t)64 * D_MODEL;
                }
                asm volatile("cp.async.commit_group;" ::: "memory");
            }
            uint32_t stg = sb + (uint32_t)((i % NSTAGE) * STAGEB);
            compute_stage(stg, stg + ASTG, warp_m, warp_n, lane, acc);
        }

        // epilogue: bias + gate + vector-red scatter
        const float* bp = b2 + e * D_MODEL + col0;
#pragma unroll
        for (int mt = 0; mt < 4; mt++) {
#pragma unroll
            for (int h = 0; h < 2; h++) {
                int r = row0 + warp_m + mt * 16 + g + h * 8;
                if (r < cnt) {
                    int   tok = g_slot_tok[e * CAP + r];
                    float w   = g_slot_w[e * CAP + r];
                    float* orow = out + (size_t)tok * D_MODEL + col0;
#pragma unroll
                    for (int nt = 0; nt < 4; nt++) {
                        int c = warp_n + nt * 8 + 2 * t4;
                        red2(orow + c,
                             (acc[mt][nt][2 * h + 0] + bp[c])     * w,
                             (acc[mt][nt][2 * h + 1] + bp[c + 1]) * w);
                    }
                }
            }
        }
    }
}

// ---------------------------------------------------------------------------
extern "C" void kernel_launch(void* const* d_in, const int* in_sizes, int n_in,
                              void* d_out, int out_size) {
    const float* x  = (const float*)d_in[0];
    const float* rw = (const float*)d_in[1];
    const float* rb = (const float*)d_in[2];
    const float* w1 = (const float*)d_in[3];
    const float* b1 = (const float*)d_in[4];
    const float* w2 = (const float*)d_in[5];
    const float* b2 = (const float*)d_in[6];
    float* out = (float*)d_out;

    cudaFuncSetAttribute(fused_gemm_kernel, cudaFuncAttributeMaxDynamicSharedMemorySize, DSMEM_BYTES);

    __half *w1h, *w2h;
    cudaGetSymbolAddress((void**)&w1h, g_w1h);
    cudaGetSymbolAddress((void**)&w2h, g_w2h);
    int wn4 = NE * D_MODEL * F_FF / 4;

    static cudaStream_t s2 = nullptr;
    static cudaEvent_t e0 = nullptr, e1 = nullptr, e2 = nullptr;
    if (!s2) {
        cudaStreamCreateWithFlags(&s2, cudaStreamNonBlocking);
        cudaEventCreateWithFlags(&e0, cudaEventDisableTiming);
        cudaEventCreateWithFlags(&e1, cudaEventDisableTiming);
        cudaEventCreateWithFlags(&e2, cudaEventDisableTiming);
    }

    // Fork converts onto s2 (branches from the capture-origin stream).
    cudaEventRecord(e0, 0);
    cudaStreamWaitEvent(s2, e0, 0);
    conv1_kernel<<<CONV_GRID, 256, 0, s2>>>((const float4*)w1, (__half2*)w1h, wn4);
    cudaEventRecord(e1, s2);                 // w1 ready
    conv2_kernel<<<CONV_GRID, 256, 0, s2>>>((const float4*)w2, (__half2*)w2h, wn4);
    cudaEventRecord(e2, s2);                 // join handle

    // Main chain.
    int n4 = out_size / 4;
    zero_kernel<<<(n4 + 255) / 256, 256>>>((float4*)out, n4);
    router_kernel<<<T_TOK / 8, 256>>>(x, rw, rb);
    rank_kernel<<<1, 256>>>();

    cudaStreamWaitEvent(0, e1, 0);           // gemm1 needs w1h
    fused_gemm_kernel<<<G1B + G2B, 256, DSMEM_BYTES>>>(b1, b2, out);
    cudaStreamWaitEvent(0, e2, 0);           // JOIN s2 back into capture stream
}

// round 17
// speedup vs baseline: 1.1167x; 1.0092x over previous
#include <cuda_runtime.h>
#include <cuda_fp16.h>
#include <cstdint>
#include <math.h>

// ---------------------------------------------------------------------------
// Problem constants
// ---------------------------------------------------------------------------
#define T_TOK   8192
#define D_MODEL 1024
#define F_FF    2048
#define NE      8
#define CAP     2560
#define NA      (T_TOK * 2)

#define BM      128
#define BN      128
#define NRB     (CAP / BM)                  // 20
#define G1B     (NE * NRB * (F_FF / BN))    // 2560
#define G2B     (NE * NRB * (D_MODEL / BN)) // 1280

#define CONV_GRID 1184

// ---------------------------------------------------------------------------
// Device scratch
// ---------------------------------------------------------------------------
__device__ __half g_xh [(size_t)T_TOK * D_MODEL];       // fp16 x
__device__ __half g_w1h[(size_t)NE * D_MODEL * F_FF];   // fp16 w1 [e][k][f]
__device__ __half g_w2h[(size_t)NE * F_FF * D_MODEL];   // fp16 w2 [e][f][d]
__device__ __half g_Hh [(size_t)NE * CAP * F_FF];       // gelu output fp16
__device__ int    g_topk_i[NA];
__device__ float  g_topk_w[NA];
__device__ int    g_slot_tok[NE * CAP];
__device__ float  g_slot_w[NE * CAP];
__device__ int    g_cnt[NE];
__device__ int    g_ready[NE * NRB];                    // gemm1 col-tile counters
__device__ int    g_w2done;                             // conv2 completion counter

// ---------------------------------------------------------------------------
// Helpers
// ---------------------------------------------------------------------------
__device__ __forceinline__ uint32_t smem_u32(const void* p) {
    uint32_t a;
    asm("{ .reg .u64 t; cvta.to.shared.u64 t, %1; cvt.u32.u64 %0, t; }" : "=r"(a) : "l"(p));
    return a;
}
__device__ __forceinline__ void cp16(uint32_t dst, const void* src) {
    asm volatile("cp.async.cg.shared.global [%0], [%1], 16;" :: "r"(dst), "l"(src));
}
__device__ __forceinline__ void mma16(float* d, const uint32_t* a, const uint32_t* b) {
    asm volatile(
        "mma.sync.aligned.m16n8k16.row.col.f32.f16.f16.f32 "
        "{%0,%1,%2,%3}, {%4,%5,%6,%7}, {%8,%9}, {%0,%1,%2,%3};"
        : "+f"(d[0]), "+f"(d[1]), "+f"(d[2]), "+f"(d[3])
        : "r"(a[0]), "r"(a[1]), "r"(a[2]), "r"(a[3]), "r"(b[0]), "r"(b[1]));
}
__device__ __forceinline__ void red2(float* p, float v0, float v1) {
    asm volatile("red.global.add.v2.f32 [%0], {%1, %2};" :: "l"(p), "f"(v0), "f"(v1) : "memory");
}
#define LDSM4(r0, r1, r2, r3, a) \
    asm volatile("ldmatrix.sync.aligned.m8n8.x4.shared.b16 {%0,%1,%2,%3}, [%4];" \
                 : "=r"(r0), "=r"(r1), "=r"(r2), "=r"(r3) : "r"(a))
#define LDSM4T(r0, r1, r2, r3, a) \
    asm volatile("ldmatrix.sync.aligned.m8n8.x4.trans.shared.b16 {%0,%1,%2,%3}, [%4];" \
                 : "=r"(r0), "=r"(r1), "=r"(r2), "=r"(r3) : "r"(a))

#define ASTG    16384                    // A: 128 m-rows * 128B
#define BSTG    16384                    // B: 64 k-rows * 256B
#define STAGEB  (ASTG + BSTG)            // 32 KB
#define NSTAGE  3
#define DSMEM_BYTES (NSTAGE * STAGEB)    // 96 KB -> 2 CTAs/SM

// ---------------------------------------------------------------------------
// K0: zero output (runs on fork stream, ahead of conv1)
// ---------------------------------------------------------------------------
__global__ void zero_kernel(float4* __restrict__ out, int n4) {
    int i = blockIdx.x * blockDim.x + threadIdx.x;
    if (i < n4) out[i] = make_float4(0.f, 0.f, 0.f, 0.f);
}

// ---------------------------------------------------------------------------
// K1a: conv w1 -> fp16; also resets g_w2done (stream-ordered before conv2)
// ---------------------------------------------------------------------------
__global__ __launch_bounds__(256)
void conv1_kernel(const float4* __restrict__ s, __half2* __restrict__ d, int n4) {
    if (blockIdx.x == 0 && threadIdx.x == 0) g_w2done = 0;
    int stride = gridDim.x * 256;
    for (int i = blockIdx.x * 256 + threadIdx.x; i < n4; i += stride) {
        float4 v = s[i];
        d[2 * i + 0] = __floats2half2_rn(v.x, v.y);
        d[2 * i + 1] = __floats2half2_rn(v.z, v.w);
    }
}

// ---------------------------------------------------------------------------
// K1b: conv w2 -> fp16; each block signals completion (gemm2 spins on it).
// Stream-ordered after zero_kernel on s2, so g_w2done also implies out==0.
// ---------------------------------------------------------------------------
__global__ __launch_bounds__(256)
void conv2_kernel(const float4* __restrict__ s, __half2* __restrict__ d, int n4) {
    int stride = gridDim.x * 256;
    for (int i = blockIdx.x * 256 + threadIdx.x; i < n4; i += stride) {
        float4 v = s[i];
        d[2 * i + 0] = __floats2half2_rn(v.x, v.y);
        d[2 * i + 1] = __floats2half2_rn(v.z, v.w);
    }
    __threadfence();
    __syncthreads();
    if (threadIdx.x == 0) atomicAdd(&g_w2done, 1);
}

// ---------------------------------------------------------------------------
// K2: router + x->fp16. rw staged in smem padded to 9 floats/row
// (conflict-free); d-loop unrolled x4 with batched LDG for MLP=4.
// ---------------------------------------------------------------------------
__global__ __launch_bounds__(256)
void router_kernel(const float* __restrict__ x,
                   const float* __restrict__ rw,
                   const float* __restrict__ rb) {
    __shared__ float rws[D_MODEL * 9];
    int tid = threadIdx.x;
    int wid = tid >> 5, lane = tid & 31;

    for (int i = tid; i < D_MODEL * NE; i += 256)
        rws[(i >> 3) * 9 + (i & 7)] = rw[i];
    __syncthreads();

    int tok = blockIdx.x * 8 + wid;
    const float* xr = x + (size_t)tok * D_MODEL;
    __half* xo = g_xh + (size_t)tok * D_MODEL;
    float acc[NE];
#pragma unroll
    for (int e = 0; e < NE; e++) acc[e] = 0.f;

#pragma unroll
    for (int d0 = 0; d0 < D_MODEL; d0 += 128) {
        int d = d0 + lane;
        float xv0 = xr[d];
        float xv1 = xr[d + 32];
        float xv2 = xr[d + 64];
        float xv3 = xr[d + 96];
        xo[d]      = __float2half_rn(xv0);
        xo[d + 32] = __float2half_rn(xv1);
        xo[d + 64] = __float2half_rn(xv2);
        xo[d + 96] = __float2half_rn(xv3);
        const float* w0 = rws + d * 9;
        const float* w1 = rws + (d + 32) * 9;
        const float* w2 = rws + (d + 64) * 9;
        const float* w3 = rws + (d + 96) * 9;
#pragma unroll
        for (int e = 0; e < NE; e++) {
            acc[e] += xv0 * w0[e];
            acc[e] += xv1 * w1[e];
            acc[e] += xv2 * w2[e];
            acc[e] += xv3 * w3[e];
        }
    }
#pragma unroll
    for (int e = 0; e < NE; e++)
#pragma unroll
        for (int o = 16; o > 0; o >>= 1)
            acc[e] += __shfl_down_sync(0xffffffffu, acc[e], o);
    if (lane == 0) {
        float l[NE];
#pragma unroll
        for (int e = 0; e < NE; e++) l[e] = acc[e] + rb[e];
        float m = l[0];
#pragma unroll
        for (int e = 1; e < NE; e++) m = fmaxf(m, l[e]);
        float p[NE], s = 0.f;
#pragma unroll
        for (int e = 0; e < NE; e++) { p[e] = expf(l[e] - m); s += p[e]; }
        float inv = 1.f / s;
#pragma unroll
        for (int e = 0; e < NE; e++) p[e] *= inv;
        int i1 = 0; float p1 = p[0];
#pragma unroll
        for (int e = 1; e < NE; e++) if (p[e] > p1) { p1 = p[e]; i1 = e; }
        int i2 = -1; float p2 = -1.f;
#pragma unroll
        for (int e = 0; e < NE; e++) if (e != i1 && p[e] > p2) { p2 = p[e]; i2 = e; }
        float sum = fmaxf(p1 + p2, 1e-9f);
        g_topk_i[tok * 2 + 0] = i1;
        g_topk_i[tok * 2 + 1] = i2;
        g_topk_w[tok * 2 + 0] = p1 / sum;
        g_topk_w[tok * 2 + 1] = p2 / sum;
    }
}

// ---------------------------------------------------------------------------
// K3: stable rank / capacity / slot table / zero readiness (single block)
// ---------------------------------------------------------------------------
__global__ void rank_kernel() {
    __shared__ int cnts[256][NE];
    int tid = threadIdx.x;
    if (tid < NE * NRB) g_ready[tid] = 0;
    int base = tid * (NA / 256);
    int local[NE];
#pragma unroll
    for (int e = 0; e < NE; e++) local[e] = 0;
    for (int a = base; a < base + NA / 256; a++) local[g_topk_i[a]]++;
#pragma unroll
    for (int e = 0; e < NE; e++) cnts[tid][e] = local[e];
    __syncthreads();
    if (tid < NE) {
        int run = 0;
        for (int i = 0; i < 256; i++) { int t = cnts[i][tid]; cnts[i][tid] = run; run += t; }
        g_cnt[tid] = min(run, CAP);
    }
    __syncthreads();
#pragma unroll
    for (int e = 0; e < NE; e++) local[e] = cnts[tid][e];
    for (int a = base; a < base + NA / 256; a++) {
        int e = g_topk_i[a];
        int r = local[e]++;
        if (r < CAP) {
            g_slot_tok[e * CAP + r] = a >> 1;
            g_slot_w[e * CAP + r] = g_topk_w[a];
        }
    }
}

// ---------------------------------------------------------------------------
// GEMM compute: one 64-half K-chunk. 8 warps 2m x 4n; warp tile 64x32.
// ---------------------------------------------------------------------------
__device__ __forceinline__ void compute_stage(uint32_t sA, uint32_t sB,
                                              int warp_m, int warp_n, int lane,
                                              float acc[4][4][4]) {
    int cg_a = lane >> 4;
    int la15 = lane & 15;
    int kl = lane & 15;
    int ng = lane >> 4;
#pragma unroll
    for (int k16 = 0; k16 < 4; k16++) {
        uint32_t af[4][4];
#pragma unroll
        for (int mt = 0; mt < 4; mt++) {
            int row = warp_m + mt * 16 + la15;
            uint32_t addr = sA + (uint32_t)(row << 7)
                          + (uint32_t)((((k16 << 1) + cg_a) ^ (row & 7)) << 4);
            LDSM4(af[mt][0], af[mt][1], af[mt][2], af[mt][3], addr);
        }
        uint32_t bf[4][2];
#pragma unroll
        for (int p = 0; p < 2; p++) {
            int kr = k16 * 16 + kl;
            int nn = warp_n + p * 16 + ng * 8;
            uint32_t addr = sB + (uint32_t)(kr << 8)
                          + (uint32_t)((((nn >> 3) ^ (kr & 7))) << 4);
            LDSM4T(bf[2 * p][0], bf[2 * p][1], bf[2 * p + 1][0], bf[2 * p + 1][1], addr);
        }
#pragma unroll
        for (int mt = 0; mt < 4; mt++)
#pragma unroll
            for (int nt = 0; nt < 4; nt++)
                mma16(acc[mt][nt], af[mt], bf[nt]);
    }
}

// ---------------------------------------------------------------------------
// K4: fused GEMM1 + GEMM2, single launch, 2 CTAs/SM.
// ---------------------------------------------------------------------------
__global__ __launch_bounds__(256, 2)
void fused_gemm_kernel(const float* __restrict__ b1,
                       const float* __restrict__ b2,
                       float* __restrict__ out) {
    extern __shared__ __align__(128) char smem[];
    uint32_t sb = smem_u32(smem);
    int tid = threadIdx.x;
    int wid = tid >> 5, lane = tid & 31;
    int warp_m = (wid >> 2) * 64, warp_n = (wid & 3) * 32;
    int g = lane >> 2, t4 = lane & 3;
    int bid = blockIdx.x;

    if (bid < G1B) {
        // ---------------- GEMM1 tile ----------------
        int cb = bid & 15;
        int erb = bid >> 4;
        int e = erb / NRB;
        int row0 = (erb % NRB) * BM;
        int cnt = g_cnt[e];
        if (row0 >= cnt) return;
        int col0 = cb * BN;

        int c8 = tid & 7;
        int rbt = tid >> 3;
        const __half* aP[4];
        uint32_t stA[4];
#pragma unroll
        for (int q = 0; q < 4; q++) {
            int r = rbt + 32 * q;
            int grow = row0 + r;
            int tok = (grow < cnt) ? g_slot_tok[e * CAP + grow] : 0;
            aP[q] = g_xh + (size_t)tok * D_MODEL + c8 * 8;
            stA[q] = sb + (uint32_t)((r << 7) + ((c8 ^ (r & 7)) << 4));
        }
        int c16 = tid & 15;
        int rk = tid >> 4;
        const __half* w1e = g_w1h + (size_t)e * D_MODEL * F_FF;
        const __half* bP[4];
        uint32_t stB[4];
#pragma unroll
        for (int q = 0; q < 4; q++) {
            int r = rk + 16 * q;
            bP[q] = w1e + (size_t)r * F_FF + col0 + c16 * 8;
            stB[q] = sb + ASTG + (uint32_t)((r << 8) + ((c16 ^ (r & 7)) << 4));
        }

        float acc[4][4][4];
#pragma unroll
        for (int mt = 0; mt < 4; mt++)
#pragma unroll
            for (int nt = 0; nt < 4; nt++)
#pragma unroll
                for (int k = 0; k < 4; k++) acc[mt][nt][k] = 0.f;

        const int NCH = D_MODEL / 64;   // 16
#pragma unroll
        for (int c = 0; c < 2; c++) {
            uint32_t so = (uint32_t)(c * STAGEB);
#pragma unroll
            for (int q = 0; q < 4; q++) {
                cp16(stA[q] + so, aP[q]); aP[q] += 64;
                cp16(stB[q] + so, bP[q]); bP[q] += (size_t)64 * F_FF;
            }
            asm volatile("cp.async.commit_group;" ::: "memory");
        }
        for (int i = 0; i < NCH; i++) {
            if (i < NCH - 1) {
                asm volatile("cp.async.wait_group 1;" ::: "memory");
            } else {
                asm volatile("cp.async.wait_group 0;" ::: "memory");
            }
            __syncthreads();
            if (i + 2 < NCH) {
                uint32_t so = (uint32_t)(((i + 2) % NSTAGE) * STAGEB);
#pragma unroll
                for (int q = 0; q < 4; q++) {
                    cp16(stA[q] + so, aP[q]); aP[q] += 64;
                    cp16(stB[q] + so, bP[q]); bP[q] += (size_t)64 * F_FF;
                }
                asm volatile("cp.async.commit_group;" ::: "memory");
            }
            uint32_t stg = sb + (uint32_t)((i % NSTAGE) * STAGEB);
            compute_stage(stg, stg + ASTG, warp_m, warp_n, lane, acc);
        }

        // epilogue: bias + gelu -> H fp16
        const float* bp = b1 + e * F_FF + col0;
#pragma unroll
        for (int mt = 0; mt < 4; mt++) {
#pragma unroll
            for (int h = 0; h < 2; h++) {
                int r = row0 + warp_m + mt * 16 + g + h * 8;
                __half* Hrow = g_Hh + ((size_t)e * CAP + r) * F_FF + col0;
#pragma unroll
                for (int nt = 0; nt < 4; nt++) {
                    int c = warp_n + nt * 8 + 2 * t4;
                    float v0 = acc[mt][nt][2 * h + 0] + bp[c];
                    float v1 = acc[mt][nt][2 * h + 1] + bp[c + 1];
                    v0 = 0.5f * v0 * (1.f + erff(v0 * 0.70710678118654752f));
                    v1 = 0.5f * v1 * (1.f + erff(v1 * 0.70710678118654752f));
                    *(__half2*)(Hrow + c) = __floats2half2_rn(v0, v1);
                }
            }
        }
        __syncthreads();
        if (tid == 0) {
            __threadfence();
            atomicAdd(&g_ready[erb], 1);
        }
    } else {
        // ---------------- GEMM2 tile ----------------
        int b2id = bid - G1B;
        int cb = b2id & 7;
        int erb = b2id >> 3;
        int e = erb / NRB;
        int row0 = (erb % NRB) * BM;
        int cnt = g_cnt[e];
        if (row0 >= cnt) return;
        int col0 = cb * BN;

        if (tid == 0) {
            while (atomicAdd(&g_w2done, 0) < CONV_GRID) __nanosleep(200);
            while (atomicAdd(&g_ready[erb], 0) < 16) __nanosleep(200);
        }
        __syncthreads();
        __threadfence();

        int c8 = tid & 7;
        int rbt = tid >> 3;
        const __half* aP[4];
        uint32_t stA[4];
        const __half* He = g_Hh + (size_t)e * CAP * F_FF;
#pragma unroll
        for (int q = 0; q < 4; q++) {
            int r = rbt + 32 * q;
            aP[q] = He + (size_t)(row0 + r) * F_FF + c8 * 8;
            stA[q] = sb + (uint32_t)((r << 7) + ((c8 ^ (r & 7)) << 4));
        }
        int c16 = tid & 15;
        int rk = tid >> 4;
        const __half* w2e = g_w2h + (size_t)e * F_FF * D_MODEL;
        const __half* bP[4];
        uint32_t stB[4];
#pragma unroll
        for (int q = 0; q < 4; q++) {
            int r = rk + 16 * q;
            bP[q] = w2e + (size_t)r * D_MODEL + col0 + c16 * 8;
            stB[q] = sb + ASTG + (uint32_t)((r << 8) + ((c16 ^ (r & 7)) << 4));
        }

        float acc[4][4][4];
#pragma unroll
        for (int mt = 0; mt < 4; mt++)
#pragma unroll
            for (int nt = 0; nt < 4; nt++)
#pragma unroll
                for (int k = 0; k < 4; k++) acc[mt][nt][k] = 0.f;

        const int NCH = F_FF / 64;   // 32
#pragma unroll
        for (int c = 0; c < 2; c++) {
            uint32_t so = (uint32_t)(c * STAGEB);
#pragma unroll
            for (int q = 0; q < 4; q++) {
                cp16(stA[q] + so, aP[q]); aP[q] += 64;
                cp16(stB[q] + so, bP[q]); bP[q] += (size_t)64 * D_MODEL;
            }
            asm volatile("cp.async.commit_group;" ::: "memory");
        }
        for (int i = 0; i < NCH; i++) {
            if (i < NCH - 1) {
                asm volatile("cp.async.wait_group 1;" ::: "memory");
            } else {
                asm volatile("cp.async.wait_group 0;" ::: "memory");
            }
            __syncthreads();
            if (i + 2 < NCH) {
                uint32_t so = (uint32_t)(((i + 2) % NSTAGE) * STAGEB);
#pragma unroll
                for (int q = 0; q < 4; q++) {
                    cp16(stA[q] + so, aP[q]); aP[q] += 64;
                    cp16(stB[q] + so, bP[q]); bP[q] += (size_t)64 * D_MODEL;
                }
                asm volatile("cp.async.commit_group;" ::: "memory");
            }
            uint32_t stg = sb + (uint32_t)((i % NSTAGE) * STAGEB);
            compute_stage(stg, stg + ASTG, warp_m, warp_n, lane, acc);
        }

        // epilogue: bias + gate + vector-red scatter
        const float* bp = b2 + e * D_MODEL + col0;
#pragma unroll
        for (int mt = 0; mt < 4; mt++) {
#pragma unroll
            for (int h = 0; h < 2; h++) {
                int r = row0 + warp_m + mt * 16 + g + h * 8;
                if (r < cnt) {
                    int   tok = g_slot_tok[e * CAP + r];
                    float w   = g_slot_w[e * CAP + r];
                    float* orow = out + (size_t)tok * D_MODEL + col0;
#pragma unroll
                    for (int nt = 0; nt < 4; nt++) {
                        int c = warp_n + nt * 8 + 2 * t4;
                        red2(orow + c,
                             (acc[mt][nt][2 * h + 0] + bp[c])     * w,
                             (acc[mt][nt][2 * h + 1] + bp[c + 1]) * w);
                    }
                }
            }
        }
    }
}

// ---------------------------------------------------------------------------
extern "C" void kernel_launch(void* const* d_in, const int* in_sizes, int n_in,
                              void* d_out, int out_size) {
    const float* x  = (const float*)d_in[0];
    const float* rw = (const float*)d_in[1];
    const float* rb = (const float*)d_in[2];
    const float* w1 = (const float*)d_in[3];
    const float* b1 = (const float*)d_in[4];
    const float* w2 = (const float*)d_in[5];
    const float* b2 = (const float*)d_in[6];
    float* out = (float*)d_out;

    cudaFuncSetAttribute(fused_gemm_kernel, cudaFuncAttributeMaxDynamicSharedMemorySize, DSMEM_BYTES);

    __half *w1h, *w2h;
    cudaGetSymbolAddress((void**)&w1h, g_w1h);
    cudaGetSymbolAddress((void**)&w2h, g_w2h);
    int wn4 = NE * D_MODEL * F_FF / 4;

    static cudaStream_t s2 = nullptr;
    static cudaEvent_t e0 = nullptr, e1 = nullptr, e2 = nullptr;
    if (!s2) {
        cudaStreamCreateWithFlags(&s2, cudaStreamNonBlocking);
        cudaEventCreateWithFlags(&e0, cudaEventDisableTiming);
        cudaEventCreateWithFlags(&e1, cudaEventDisableTiming);
        cudaEventCreateWithFlags(&e2, cudaEventDisableTiming);
    }

    // Fork: zero + converts on s2 (zero precedes conv1, so g_w2done also
    // implies out is zeroed by stream order on s2).
    cudaEventRecord(e0, 0);
    cudaStreamWaitEvent(s2, e0, 0);
    int n4 = out_size / 4;
    zero_kernel<<<(n4 + 255) / 256, 256, 0, s2>>>((float4*)out, n4);
    conv1_kernel<<<CONV_GRID, 256, 0, s2>>>((const float4*)w1, (__half2*)w1h, wn4);
    cudaEventRecord(e1, s2);                 // zero + w1 ready
    conv2_kernel<<<CONV_GRID, 256, 0, s2>>>((const float4*)w2, (__half2*)w2h, wn4);
    cudaEventRecord(e2, s2);                 // join handle

    // Main chain.
    router_kernel<<<T_TOK / 8, 256>>>(x, rw, rb);
    rank_kernel<<<1, 256>>>();

    cudaStreamWaitEvent(0, e1, 0);           // gemm1 needs w1h (+ out zeroed)
    fused_gemm_kernel<<<G1B + G2B, 256, DSMEM_BYTES>>>(b1, b2, out);
    cudaStreamWaitEvent(0, e2, 0);           // JOIN s2 back into capture stream
}